// round 1
// baseline (speedup 1.0000x reference)
#include <cuda_runtime.h>

// LoRAConv3d: B=2, CIN=64, COUT=128, K=3x3x3, stride=1, pad=1, dil=1,
// RANK=16, SCALING=2.0, spatial 32^3.
//
// out = conv(x, W) + bias + 2 * boxsum3x3x3( conv(x, A) ) @ B^T
//
// Kernel 1: 144-output-channel direct conv (128 -> d_out with bias, 16 -> g_low)
// Kernel 2: per-position 3x3x3 boxsum of the 16 "low" channels + [128x16] matvec,
//           accumulated into d_out.

#define SPD 32
#define TD 4
#define TH 8
#define TW 8
// tiles: 8 (z) x 4 (y) x 4 (x) = 128 per batch

__device__ float g_low[2 * 16 * 32768];  // [b][r][z][y][x], 4 MB scratch

// ---------------------------------------------------------------------------
// Kernel 1: direct conv, chunk of 16 output channels per block.
// blockIdx.x = oc chunk (0..8): 0..7 -> base weight, 8 -> lora_A rows
// blockIdx.y = spatial tile (0..127), blockIdx.z = batch
// 128 threads: tid/64 -> oc half (8 oc), tid%64 -> (y,x) in tile; each thread
// covers z = 0..3 of the tile. Accumulators: 8 oc x 4 z = 32 regs.
// ---------------------------------------------------------------------------
__global__ __launch_bounds__(128) void conv144_kernel(
    const float* __restrict__ x,
    const float* __restrict__ weight,
    const float* __restrict__ bias,
    const float* __restrict__ lora_A,
    float* __restrict__ out)
{
    __shared__ float sx[8 * 6 * 10 * 10];   // 8 cin x (4+2) x (8+2) x (8+2) = 4800 f
    __shared__ float sw[16 * 8 * 27];       // 16 oc x 8 cin x 27 = 3456 f

    const int chunk = blockIdx.x;           // 0..8
    const int tile  = blockIdx.y;           // 0..127
    const int b     = blockIdx.z;

    const int tz0 = (tile >> 4) * TD;
    const int ty0 = ((tile >> 2) & 3) * TH;
    const int tx0 = (tile & 3) * TW;

    const int tid    = threadIdx.x;
    const int oc_sub = tid >> 6;            // 0 or 1
    const int pg     = tid & 63;
    const int py     = pg >> 3;
    const int px     = pg & 7;

    const bool is_low = (chunk == 8);
    const float* wsrc = is_low ? lora_A : weight;
    const int oc_g0   = is_low ? 0 : chunk * 16;

    float acc[8][4];
#pragma unroll
    for (int j = 0; j < 8; ++j)
#pragma unroll
        for (int z = 0; z < 4; ++z) acc[j][z] = 0.f;

    for (int cb = 0; cb < 8; ++cb) {
        __syncthreads();
        // load input tile for cin = cb*8 .. cb*8+7 with -1 halo, zero-padded
        for (int i = tid; i < 4800; i += 128) {
            int c    = i / 600;
            int rem  = i - c * 600;
            int zz   = rem / 100;
            int rem2 = rem - zz * 100;
            int yy   = rem2 / 10;
            int xx   = rem2 - yy * 10;
            int gz = tz0 + zz - 1, gy = ty0 + yy - 1, gx = tx0 + xx - 1;
            float v = 0.f;
            if ((unsigned)gz < 32u && (unsigned)gy < 32u && (unsigned)gx < 32u)
                v = x[(b * 64 + cb * 8 + c) * 32768 + gz * 1024 + gy * 32 + gx];
            sx[i] = v;
        }
        // load 16 oc x 8 cin x 27 weights (contiguous 216 floats per oc row)
        for (int i = tid; i < 3456; i += 128) {
            int oc  = i / 216;
            int rem = i - oc * 216;         // c_local*27 + off
            sw[i] = wsrc[(oc_g0 + oc) * 1728 + cb * 216 + rem];
        }
        __syncthreads();

        for (int c = 0; c < 8; ++c) {
            const float* swc = &sw[oc_sub * 8 * 216 + c * 27];
            const int xbase_c = c * 600;
#pragma unroll
            for (int kd = 0; kd < 3; ++kd) {
#pragma unroll
                for (int kh = 0; kh < 3; ++kh) {
#pragma unroll
                    for (int kw = 0; kw < 3; ++kw) {
                        const int off = (kd * 3 + kh) * 3 + kw;
                        const int xb  = xbase_c + kd * 100 + (py + kh) * 10 + (px + kw);
                        float xv[4];
#pragma unroll
                        for (int z = 0; z < 4; ++z) xv[z] = sx[xb + z * 100];
#pragma unroll
                        for (int j = 0; j < 8; ++j) {
                            const float wv = swc[j * 216 + off];
#pragma unroll
                            for (int z = 0; z < 4; ++z)
                                acc[j][z] = fmaf(wv, xv[z], acc[j][z]);
                        }
                    }
                }
            }
        }
    }

    const int sp = (ty0 + py) * 32 + (tx0 + px);
    if (!is_low) {
#pragma unroll
        for (int j = 0; j < 8; ++j) {
            const int oc = chunk * 16 + oc_sub * 8 + j;
            const float bv = bias[oc];
#pragma unroll
            for (int z = 0; z < 4; ++z)
                out[(b * 128 + oc) * 32768 + (tz0 + z) * 1024 + sp] = acc[j][z] + bv;
        }
    } else {
#pragma unroll
        for (int j = 0; j < 8; ++j) {
            const int r = oc_sub * 8 + j;
#pragma unroll
            for (int z = 0; z < 4; ++z)
                g_low[(b * 16 + r) * 32768 + (tz0 + z) * 1024 + sp] = acc[j][z];
        }
    }
}

// ---------------------------------------------------------------------------
// Kernel 2: boxsum(low) then out += 2 * B @ lowsum.
// blockIdx.x = spatial tile (0..127), blockIdx.y = batch. 256 threads = one per
// position of the 4x8x8 tile.
// ---------------------------------------------------------------------------
__global__ __launch_bounds__(256) void lora_apply_kernel(
    const float* __restrict__ lora_B,
    float* __restrict__ out)
{
    __shared__ float slow[8 * 6 * 10 * 10];  // 8 r x halo tile = 4800 f
    __shared__ float sB[128 * 16];

    const int tile = blockIdx.x;
    const int b    = blockIdx.y;
    const int tz0 = (tile >> 4) * TD;
    const int ty0 = ((tile >> 2) & 3) * TH;
    const int tx0 = (tile & 3) * TW;

    const int tid = threadIdx.x;
    const int pz = tid >> 6;
    const int py = (tid >> 3) & 7;
    const int px = tid & 7;

    for (int i = tid; i < 2048; i += 256) sB[i] = lora_B[i];

    float ls[16];
    for (int rc = 0; rc < 2; ++rc) {
        __syncthreads();
        for (int i = tid; i < 4800; i += 256) {
            int r    = i / 600;
            int rem  = i - r * 600;
            int zz   = rem / 100;
            int rem2 = rem - zz * 100;
            int yy   = rem2 / 10;
            int xx   = rem2 - yy * 10;
            int gz = tz0 + zz - 1, gy = ty0 + yy - 1, gx = tx0 + xx - 1;
            float v = 0.f;
            if ((unsigned)gz < 32u && (unsigned)gy < 32u && (unsigned)gx < 32u)
                v = g_low[(b * 16 + rc * 8 + r) * 32768 + gz * 1024 + gy * 32 + gx];
            slow[i] = v;
        }
        __syncthreads();
#pragma unroll
        for (int r = 0; r < 8; ++r) {
            const int base = r * 600 + pz * 100 + py * 10 + px;
            float s = 0.f;
#pragma unroll
            for (int kd = 0; kd < 3; ++kd)
#pragma unroll
                for (int kh = 0; kh < 3; ++kh)
#pragma unroll
                    for (int kw = 0; kw < 3; ++kw)
                        s += slow[base + kd * 100 + kh * 10 + kw];
            ls[rc * 8 + r] = s;
        }
    }

    const int sp = (tz0 + pz) * 1024 + (ty0 + py) * 32 + (tx0 + px);
#pragma unroll 4
    for (int oc = 0; oc < 128; ++oc) {
        float d = 0.f;
#pragma unroll
        for (int r = 0; r < 16; ++r) d = fmaf(sB[oc * 16 + r], ls[r], d);
        const int idx = (b * 128 + oc) * 32768 + sp;
        out[idx] = out[idx] + 2.0f * d;
    }
}

extern "C" void kernel_launch(void* const* d_in, const int* in_sizes, int n_in,
                              void* d_out, int out_size)
{
    const float* x      = (const float*)d_in[0];
    const float* weight = (const float*)d_in[1];
    const float* bias   = (const float*)d_in[2];
    const float* lora_A = (const float*)d_in[3];
    const float* lora_B = (const float*)d_in[4];
    float* out = (float*)d_out;

    dim3 gA(9, 128, 2);
    conv144_kernel<<<gA, 128>>>(x, weight, bias, lora_A, out);

    dim3 gB(128, 2);
    lora_apply_kernel<<<gB, 256>>>(lora_B, out);
}

// round 3
// speedup vs baseline: 5.6279x; 5.6279x over previous
#include <cuda_runtime.h>
#include <cuda_fp16.h>
#include <cstdint>

// LoRAConv3d: out = conv3(x,[W;A]) -> (base+bias, low); out += 2*B@boxsum3(low)
// Implicit GEMM on mma.sync.m16n8k16 (f16 in, f32 acc).
// B=2, CIN=64, COUT=128, RANK=16, K=3^3, spatial 32^3, pad 1.

__device__ __half  xpad[2 * 34 * 34 * 34 * 64];   // padded NDHWC fp16 (zero border)
__device__ __half  wk[27 * 144 * 64];             // [off][n][c]
__device__ float   g_low[2 * 16 * 32768];
__device__ float   g_ls[2 * 16 * 32768];

// ---------------- helpers ----------------
__device__ __forceinline__ uint32_t smem_u32(const void* p) {
    uint32_t a;
    asm("{ .reg .u64 t; cvta.to.shared.u64 t, %1; cvt.u32.u64 %0, t; }" : "=r"(a) : "l"(p));
    return a;
}
__device__ __forceinline__ void cp16(uint32_t dst, const void* src) {
    asm volatile("cp.async.cg.shared.global [%0], [%1], 16;" :: "r"(dst), "l"(src));
}
__device__ __forceinline__ void cp_commit() { asm volatile("cp.async.commit_group;"); }
template <int N> __device__ __forceinline__ void cp_wait() {
    asm volatile("cp.async.wait_group %0;" :: "n"(N) : "memory");
}
__device__ __forceinline__ void ldsm4(uint32_t* r, uint32_t addr) {
    asm volatile("ldmatrix.sync.aligned.m8n8.x4.shared.b16 {%0,%1,%2,%3}, [%4];"
                 : "=r"(r[0]), "=r"(r[1]), "=r"(r[2]), "=r"(r[3]) : "r"(addr));
}
__device__ __forceinline__ void ldsm2(uint32_t& b0, uint32_t& b1, uint32_t addr) {
    asm volatile("ldmatrix.sync.aligned.m8n8.x2.shared.b16 {%0,%1}, [%2];"
                 : "=r"(b0), "=r"(b1) : "r"(addr));
}
__device__ __forceinline__ void mma16816(float* c, const uint32_t* a,
                                         uint32_t b0, uint32_t b1) {
    asm volatile(
        "mma.sync.aligned.m16n8k16.row.col.f32.f16.f16.f32 "
        "{%0,%1,%2,%3}, {%4,%5,%6,%7}, {%8,%9}, {%0,%1,%2,%3};"
        : "+f"(c[0]), "+f"(c[1]), "+f"(c[2]), "+f"(c[3])
        : "r"(a[0]), "r"(a[1]), "r"(a[2]), "r"(a[3]), "r"(b0), "r"(b1));
}

// ---------------- prep kernels ----------------
__global__ void zero_xpad_kernel() {
    uint32_t* p = reinterpret_cast<uint32_t*>(xpad);
    int i = blockIdx.x * 1024 + threadIdx.x;
    if (i < (2 * 34 * 34 * 34 * 64) / 2) p[i] = 0u;
}

__global__ __launch_bounds__(256) void pad_x_kernel(const float* __restrict__ x) {
    int id = blockIdx.x;                       // (b,z,y)
    int b = id >> 10, z = (id >> 5) & 31, y = id & 31;
    __shared__ float s[2048];                  // [c][x]
    for (int i = threadIdx.x; i < 2048; i += 256) {
        int c = i >> 5, xx = i & 31;
        s[i] = x[((b * 64 + c) << 15) + (z << 10) + (y << 5) + xx];
    }
    __syncthreads();
    for (int i = threadIdx.x; i < 2048; i += 256) {
        int c = i & 63, xx = i >> 6;
        xpad[(size_t)(((b * 34 + z + 1) * 34 + (y + 1)) * 34 + (xx + 1)) * 64 + c] =
            __float2half(s[(c << 5) + xx]);
    }
}

__global__ void prep_w_kernel(const float* __restrict__ weight,
                              const float* __restrict__ lora_A) {
    int i = blockIdx.x * 256 + threadIdx.x;    // 27*144*64
    if (i >= 27 * 144 * 64) return;
    int c = i & 63;
    int n = (i >> 6) % 144;
    int off = i / 9216;
    float v = (n < 128) ? weight[n * 1728 + c * 27 + off]
                        : lora_A[(n - 128) * 1728 + c * 27 + off];
    wk[i] = __float2half(v);
}

// ---------------- main conv: implicit GEMM on mma.sync ----------------
// per CTA: M=128 positions (1z x 4y x 32x), N=144, loop 27 offsets (K=64 each).
// smem: A halo 612 rows (3z*6y*34x) x 144B; B double buf 2 x 144x144B; bias.
#define SA_BYTES   (612 * 144)                 // 88128
#define SB_STRIDE  (144 * 144)                 // 20736
#define SB_OFF     SA_BYTES
#define SBIAS_OFF  (SA_BYTES + 2 * SB_STRIDE)  // 129600
#define SMEM_TOTAL (SBIAS_OFF + 512)           // 130112

__device__ __forceinline__ void stage_B(uint32_t buf, int off, int tid) {
    const char* wb = (const char*)wk + (size_t)off * 18432;
    for (int i = tid; i < 1152; i += 256) {
        int row = i >> 3, k = i & 7;
        cp16(buf + row * 144 + k * 16, wb + row * 128 + k * 16);
    }
}

__global__ __launch_bounds__(256, 1) void conv_mma_kernel(
    const float* __restrict__ bias, float* __restrict__ out)
{
    extern __shared__ char smem[];
    const uint32_t sb = smem_u32(smem);
    const uint32_t sA = sb, sB = sb + SB_OFF;
    float* sbias = (float*)(smem + SBIAS_OFF);

    const int tid = threadIdx.x, lane = tid & 31, wid = tid >> 5;
    const int t = blockIdx.x;                  // 512 tiles
    const int b = t >> 8, z0 = (t >> 3) & 31, y0 = (t & 7) << 2;

    if (tid < 128) sbias[tid] = bias[tid];

    // stage A halo: rows r = (dz*6+yi)*34 + xi, dz:0..2, yi:0..5, xi:0..33
    {
        const char* xb = (const char*)xpad;
        for (int i = tid; i < 4896; i += 256) {
            int r = i >> 3, k = i & 7;
            int dz = r / 204, rem = r - dz * 204;
            int yi = rem / 34, xi = rem - yi * 34;
            size_t src = ((size_t)(((b * 34 + z0 + dz) * 34 + (y0 + yi)) * 34 + xi)) * 128
                         + k * 16;
            cp16(sA + r * 144 + k * 16, xb + src);
        }
    }
    stage_B(sB, 0, tid);
    cp_commit();

    // lane constants
    const int m0w = (wid >> 1) * 32;           // m-band base
    const int n0w = (wid & 1) * 72;            // n-half base
    uint32_t laneA[2];
#pragma unroll
    for (int mi = 0; mi < 2; ++mi) {
        int m = m0w + mi * 16 + (lane & 15);
        int yi = m >> 5, xi = m & 31;
        laneA[mi] = (uint32_t)((yi * 34 + xi) * 144 + ((lane >> 4) << 4));
    }
    const uint32_t laneB = (uint32_t)((n0w + (lane & 7)) * 144 + ((lane >> 3) & 1) * 16);

    float acc[2][9][4];
#pragma unroll
    for (int mi = 0; mi < 2; ++mi)
#pragma unroll
        for (int nj = 0; nj < 9; ++nj)
#pragma unroll
            for (int q = 0; q < 4; ++q) acc[mi][nj][q] = 0.f;

    for (int off = 0; off < 27; ++off) {
        cp_wait<0>();
        __syncthreads();
        if (off < 26) {
            stage_B(sB + ((off + 1) & 1) * SB_STRIDE, off + 1, tid);
            cp_commit();
        }
        const int dz = off / 9, r9 = off - dz * 9;
        const int dy = r9 / 3, dx = r9 - dy * 3;
        const uint32_t aoff = sA + (uint32_t)((dz * 204 + dy * 34 + dx) * 144);
        const uint32_t bbuf = sB + (off & 1) * SB_STRIDE + laneB;

#pragma unroll
        for (int s = 0; s < 4; ++s) {
            uint32_t a0[4], a1[4];
            ldsm4(a0, aoff + laneA[0] + s * 32);
            ldsm4(a1, aoff + laneA[1] + s * 32);
#pragma unroll
            for (int nj = 0; nj < 9; ++nj) {
                uint32_t b0, b1;
                ldsm2(b0, b1, bbuf + nj * 1152 + s * 32);
                mma16816(acc[0][nj], a0, b0, b1);
                mma16816(acc[1][nj], a1, b0, b1);
            }
        }
    }

    // epilogue: fragment (mi,nj) -> rows m, cols n
#pragma unroll
    for (int mi = 0; mi < 2; ++mi) {
        const int r0 = m0w + mi * 16 + (lane >> 2);
        const int r1 = r0 + 8;
        const int pos0 = z0 * 1024 + (y0 + (r0 >> 5)) * 32 + (r0 & 31);
        const int pos1 = z0 * 1024 + (y0 + (r1 >> 5)) * 32 + (r1 & 31);
#pragma unroll
        for (int nj = 0; nj < 9; ++nj) {
            const int c0 = n0w + nj * 8 + ((lane & 3) << 1);
#pragma unroll
            for (int q = 0; q < 4; ++q) {
                const int c = c0 + (q & 1);
                const int pos = (q < 2) ? pos0 : pos1;
                const float v = acc[mi][nj][q];
                if (c < 128)
                    out[(size_t)(b * 128 + c) * 32768 + pos] = v + sbias[c];
                else
                    g_low[(size_t)(b * 16 + (c - 128)) * 32768 + pos] = v;
            }
        }
    }
}

// ---------------- lora epilogue ----------------
__global__ __launch_bounds__(1024) void boxsum_kernel() {
    int id = blockIdx.x;                 // (b*16+r)*32 + z
    int z = id & 31, br = id >> 5;
    __shared__ float s[3 * 34 * 34];
    int tid = threadIdx.x;
    for (int i = tid; i < 3 * 34 * 34; i += 1024) s[i] = 0.f;
    __syncthreads();
    int y = tid >> 5, xx = tid & 31;
    const float* base = g_low + (size_t)br * 32768;
#pragma unroll
    for (int zz = 0; zz < 3; ++zz) {
        int zin = z - 1 + zz;
        if ((unsigned)zin < 32u)
            s[zz * 1156 + (y + 1) * 34 + (xx + 1)] = base[zin * 1024 + y * 32 + xx];
    }
    __syncthreads();
    float a = 0.f;
#pragma unroll
    for (int zz = 0; zz < 3; ++zz)
#pragma unroll
        for (int dy = 0; dy < 3; ++dy)
#pragma unroll
            for (int dw = 0; dw < 3; ++dw)
                a += s[zz * 1156 + (y + dy) * 34 + (xx + dw)];
    g_ls[(size_t)br * 32768 + z * 1024 + y * 32 + xx] = a;
}

__global__ __launch_bounds__(1024) void lora_out_kernel(
    const float* __restrict__ lora_B, float* __restrict__ out)
{
    int id = blockIdx.x;                 // ((b*32)+z)*8 + og
    int og = id & 7, z = (id >> 3) & 31, b = id >> 8;
    __shared__ float sB[256];
    int tid = threadIdx.x;
    if (tid < 256) sB[tid] = lora_B[og * 256 + tid];
    float ls[16];
    int pos = z * 1024 + tid;
#pragma unroll
    for (int r = 0; r < 16; ++r)
        ls[r] = g_ls[(size_t)(b * 16 + r) * 32768 + pos];
    __syncthreads();
#pragma unroll
    for (int o = 0; o < 16; ++o) {
        float d = 0.f;
#pragma unroll
        for (int r = 0; r < 16; ++r) d = fmaf(sB[o * 16 + r], ls[r], d);
        size_t idx = (size_t)(b * 128 + og * 16 + o) * 32768 + pos;
        out[idx] += 2.0f * d;
    }
}

// ---------------- launch ----------------
extern "C" void kernel_launch(void* const* d_in, const int* in_sizes, int n_in,
                              void* d_out, int out_size)
{
    const float* x      = (const float*)d_in[0];
    const float* weight = (const float*)d_in[1];
    const float* bias   = (const float*)d_in[2];
    const float* lora_A = (const float*)d_in[3];
    const float* lora_B = (const float*)d_in[4];
    float* out = (float*)d_out;

    static bool attr_set = false;
    if (!attr_set) {
        cudaFuncSetAttribute(conv_mma_kernel,
                             cudaFuncAttributeMaxDynamicSharedMemorySize, SMEM_TOTAL);
        attr_set = true;
    }

    zero_xpad_kernel<<<2457, 1024>>>();
    pad_x_kernel<<<2048, 256>>>(x);
    prep_w_kernel<<<(27 * 144 * 64 + 255) / 256, 256>>>(weight, lora_A);
    conv_mma_kernel<<<512, 256, SMEM_TOTAL>>>(bias, out);
    boxsum_kernel<<<1024, 1024>>>();
    lora_out_kernel<<<512, 1024>>>(lora_B, out);
}